// round 6
// baseline (speedup 1.0000x reference)
#include <cuda_runtime.h>
#include <cuda_bf16.h>
#include <cstdint>

// ---------------- Problem constants ----------------
#define EMBED   256
#define HEADS   8
#define LEVELS  4
#define POINTS  4
#define CDIM    32
#define LEN_V   5440
#define LEN_Q   5440
#define BSZ     4
#define MROWS   (BSZ * LEN_Q)   // 21760

// ---------------- Scratch ----------------
__device__ float g_v   [(size_t)MROWS * EMBED];
__device__ float g_off [(size_t)MROWS * EMBED];
__device__ float g_awl [(size_t)MROWS * 128];
__device__ float g_samp[(size_t)MROWS * EMBED];

// split-bf16 activations: slot0 = value (later reused for samp), slot1 = query
__device__ __nv_bfloat16 g_a0h[(size_t)MROWS * EMBED];
__device__ __nv_bfloat16 g_a0l[(size_t)MROWS * EMBED];
__device__ __nv_bfloat16 g_a1h[(size_t)MROWS * EMBED];
__device__ __nv_bfloat16 g_a1l[(size_t)MROWS * EMBED];

// transposed split weights: [N,K] bf16, offsets {vproj:0, off:65536, attn:131072, out:163840}
__device__ __nv_bfloat16 g_wth[229376];
__device__ __nv_bfloat16 g_wtl[229376];

// ---------------- PTX helpers (generic ISA only — no sm_103a-gated instrs) --
__device__ __forceinline__ uint32_t smem_u32(const void* p) {
    uint32_t a;
    asm("{ .reg .u64 t; cvta.to.shared.u64 t, %1; cvt.u32.u64 %0, t; }" : "=r"(a) : "l"(p));
    return a;
}
__device__ __forceinline__ void ldm_x4(uint32_t* r, uint32_t addr) {
    asm volatile("ldmatrix.sync.aligned.m8n8.x4.shared.b16 {%0,%1,%2,%3}, [%4];"
        : "=r"(r[0]), "=r"(r[1]), "=r"(r[2]), "=r"(r[3]) : "r"(addr));
}
__device__ __forceinline__ void mma16816(float* c, const uint32_t* a, const uint32_t* b) {
    asm volatile(
        "mma.sync.aligned.m16n8k16.row.col.f32.bf16.bf16.f32 "
        "{%0,%1,%2,%3}, {%4,%5,%6,%7}, {%8,%9}, {%0,%1,%2,%3};"
        : "+f"(c[0]), "+f"(c[1]), "+f"(c[2]), "+f"(c[3])
        : "r"(a[0]), "r"(a[1]), "r"(a[2]), "r"(a[3]), "r"(b[0]), "r"(b[1]));
}

// swizzled smem offset (elements): row stride 64 bf16, 16B chunk xor (row&7)
__device__ __forceinline__ int swz(int row, int k) {
    return row * 64 + ((((k >> 3) ^ row) & 7) << 3) + (k & 7);
}

// ---------------- GEMM: C[M,Ntot] = A * W^T + bias, split-bf16 on HMMA ------
// BM=128, BN=64, BK=64, 256 threads = 8 warps (4 m x 2 n), warp tile 32x32.
// 3 passes: Ah*Bh + Ah*Bl + Al*Bh into shared fp32 accumulators.
__global__ __launch_bounds__(256)
void gemm_bf16split(const __nv_bfloat16* __restrict__ Ah, const __nv_bfloat16* __restrict__ Al,
                    const __nv_bfloat16* __restrict__ BTh, const __nv_bfloat16* __restrict__ BTl,
                    const float* __restrict__ bias, float* __restrict__ C, int Ntot)
{
    __shared__ __nv_bfloat16 sAh[128 * 64], sAl[128 * 64];
    __shared__ __nv_bfloat16 sBh[64 * 64],  sBl[64 * 64];

    const int tid  = threadIdx.x;
    const int lane = tid & 31;
    const int wid  = tid >> 5;
    const int wm   = wid & 3;        // 4 warps over M (32 rows each)
    const int wn   = wid >> 2;       // 2 warps over N (32 cols each)
    const int bm   = blockIdx.x * 128;
    const int bn   = blockIdx.y * 64;

    const __nv_bfloat16* pAh = Ah  + (size_t)bm * EMBED;
    const __nv_bfloat16* pAl = Al  + (size_t)bm * EMBED;
    const __nv_bfloat16* pBh = BTh + (size_t)bn * EMBED;
    const __nv_bfloat16* pBl = BTl + (size_t)bn * EMBED;

    const uint32_t uAh = smem_u32(sAh), uAl = smem_u32(sAl);
    const uint32_t uBh = smem_u32(sBh), uBl = smem_u32(sBl);

    float c[2][4][4];
    #pragma unroll
    for (int mt = 0; mt < 2; ++mt)
        #pragma unroll
        for (int nt = 0; nt < 4; ++nt)
            #pragma unroll
            for (int i = 0; i < 4; ++i) c[mt][nt][i] = 0.f;

    const int grow = tid >> 3;      // 0..31
    const int gc8  = tid & 7;       // 16B chunk within 64-elem row

    // fragment smem addresses (byte), per lane, k-part added per step
    // A: rows (lane&15), col-half (lane>>4)*8
    const int a_r = (lane & 15);
    const int a_k = (lane >> 4) << 3;
    // B: n = ((lane>>4)<<3) + (lane&7), k-half ((lane>>3)&1)*8
    const int b_n = ((lane >> 4) << 3) + (lane & 7);
    const int b_k = ((lane >> 3) & 1) << 3;

    #pragma unroll
    for (int kc = 0; kc < 4; ++kc) {
        // ---- load chunk kc into smem (swizzled) ----
        #pragma unroll
        for (int t = 0; t < 4; ++t) {
            const int row = grow + t * 32;
            const float4 vh = *(const float4*)(pAh + (size_t)row * EMBED + kc * 64 + gc8 * 8);
            const float4 vl = *(const float4*)(pAl + (size_t)row * EMBED + kc * 64 + gc8 * 8);
            *(float4*)(sAh + swz(row, gc8 * 8)) = vh;
            *(float4*)(sAl + swz(row, gc8 * 8)) = vl;
        }
        #pragma unroll
        for (int t = 0; t < 2; ++t) {
            const int row = grow + t * 32;
            const float4 vh = *(const float4*)(pBh + (size_t)row * EMBED + kc * 64 + gc8 * 8);
            const float4 vl = *(const float4*)(pBl + (size_t)row * EMBED + kc * 64 + gc8 * 8);
            *(float4*)(sBh + swz(row, gc8 * 8)) = vh;
            *(float4*)(sBl + swz(row, gc8 * 8)) = vl;
        }
        __syncthreads();

        // ---- compute: 4 k16 steps ----
        #pragma unroll
        for (int ks = 0; ks < 4; ++ks) {
            uint32_t ah[2][4], al[2][4], bh[4][2], bl[4][2];
            #pragma unroll
            for (int mt = 0; mt < 2; ++mt) {
                const int r = wm * 32 + mt * 16 + a_r;
                const int k = ks * 16 + a_k;
                ldm_x4(ah[mt], uAh + swz(r, k) * 2);
                ldm_x4(al[mt], uAl + swz(r, k) * 2);
            }
            #pragma unroll
            for (int np = 0; np < 2; ++np) {     // pairs of n8-tiles
                const int n = wn * 32 + np * 16 + b_n;
                const int k = ks * 16 + b_k;
                uint32_t th[4], tl[4];
                ldm_x4(th, uBh + swz(n, k) * 2);
                ldm_x4(tl, uBl + swz(n, k) * 2);
                bh[np * 2 + 0][0] = th[0]; bh[np * 2 + 0][1] = th[1];
                bh[np * 2 + 1][0] = th[2]; bh[np * 2 + 1][1] = th[3];
                bl[np * 2 + 0][0] = tl[0]; bl[np * 2 + 0][1] = tl[1];
                bl[np * 2 + 1][0] = tl[2]; bl[np * 2 + 1][1] = tl[3];
            }
            #pragma unroll
            for (int mt = 0; mt < 2; ++mt)
                #pragma unroll
                for (int nt = 0; nt < 4; ++nt) {
                    mma16816(c[mt][nt], ah[mt], bh[nt]);
                    mma16816(c[mt][nt], ah[mt], bl[nt]);
                    mma16816(c[mt][nt], al[mt], bh[nt]);
                }
        }
        __syncthreads();
    }

    // ---- epilogue: bias + store ----
    #pragma unroll
    for (int mt = 0; mt < 2; ++mt) {
        const int r0 = bm + wm * 32 + mt * 16 + (lane >> 2);
        #pragma unroll
        for (int nt = 0; nt < 4; ++nt) {
            const int col = bn + wn * 32 + nt * 8 + (lane & 3) * 2;
            const float2 bv = *(const float2*)(bias + col);
            float2 o0, o1;
            o0.x = c[mt][nt][0] + bv.x; o0.y = c[mt][nt][1] + bv.y;
            o1.x = c[mt][nt][2] + bv.x; o1.y = c[mt][nt][3] + bv.y;
            *(float2*)(C + (size_t)r0 * Ntot + col)       = o0;
            *(float2*)(C + (size_t)(r0 + 8) * Ntot + col) = o1;
        }
    }
}

// ---------------- split-bf16 conversions ----------------
__global__ __launch_bounds__(256)
void conv_act(const float* __restrict__ s0, const float* __restrict__ s1,
              __nv_bfloat16* __restrict__ d0h, __nv_bfloat16* __restrict__ d0l,
              __nv_bfloat16* __restrict__ d1h, __nv_bfloat16* __restrict__ d1l)
{
    const float* s = blockIdx.y ? s1 : s0;
    __nv_bfloat16* dh = blockIdx.y ? d1h : d0h;
    __nv_bfloat16* dl = blockIdx.y ? d1l : d0l;
    const size_t i = (size_t)blockIdx.x * 256 + threadIdx.x;
    float4 x = ((const float4*)s)[i];
    union { __nv_bfloat16 b[4]; uint2 u; } H, L;
    float xs[4] = {x.x, x.y, x.z, x.w};
    #pragma unroll
    for (int j = 0; j < 4; ++j) {
        H.b[j] = __float2bfloat16(xs[j]);
        L.b[j] = __float2bfloat16(xs[j] - __bfloat162float(H.b[j]));
    }
    ((uint2*)dh)[i] = H.u;
    ((uint2*)dl)[i] = L.u;
}

// transpose + split weights: out[n*256 + k] = W[k*N + n]
__global__ __launch_bounds__(256)
void conv_wt(const float* __restrict__ w0, const float* __restrict__ w1,
             const float* __restrict__ w2, const float* __restrict__ w3)
{
    const int m = blockIdx.y;
    const float* W = (m == 0) ? w0 : (m == 1) ? w1 : (m == 2) ? w2 : w3;
    const int N   = (m == 2) ? 128 : 256;
    const int off = (m == 0) ? 0 : (m == 1) ? 65536 : (m == 2) ? 131072 : 163840;
    const int idx = blockIdx.x * 256 + threadIdx.x;
    if (idx >= N * 256) return;
    const int k = idx & 255, n = idx >> 8;
    const float x = W[(size_t)k * N + n];
    __nv_bfloat16 h = __float2bfloat16(x);
    g_wth[off + idx] = h;
    g_wtl[off + idx] = __float2bfloat16(x - __bfloat162float(h));
}

// ---------------- Sampling kernel (point-parallel lanes) ----------------
__global__ __launch_bounds__(256)
void msda_sample(const float* __restrict__ ref, float* __restrict__ samp)
{
    const int bq   = blockIdx.x;
    const int b    = bq / LEN_Q;
    const int h    = threadIdx.x >> 5;
    const int lane = threadIdx.x & 31;
    const int p4   = lane >> 3;
    const int cg   = lane & 7;

    const float* off = g_off + (size_t)bq * EMBED + h * 32;
    const float* awl = g_awl + (size_t)bq * 128 + h * 16;
    const float* vb  = g_v + (size_t)b * LEN_V * EMBED + h * CDIM + cg * 4;
    const float* rp  = ref + (size_t)bq * 8;

    float4 r01 = ((const float4*)rp)[0];
    float4 r23 = ((const float4*)rp)[1];
    const float rx[4] = {r01.x, r01.z, r23.x, r23.z};
    const float ry[4] = {r01.y, r01.w, r23.y, r23.w};

    float e[4];
    e[0] = awl[p4]; e[1] = awl[4 + p4]; e[2] = awl[8 + p4]; e[3] = awl[12 + p4];
    float mx = fmaxf(fmaxf(e[0], e[1]), fmaxf(e[2], e[3]));
    mx = fmaxf(mx, __shfl_xor_sync(0xffffffffu, mx, 8));
    mx = fmaxf(mx, __shfl_xor_sync(0xffffffffu, mx, 16));
    float s = 0.f;
    #pragma unroll
    for (int l = 0; l < 4; ++l) { e[l] = __expf(e[l] - mx); s += e[l]; }
    s += __shfl_xor_sync(0xffffffffu, s, 8);
    s += __shfl_xor_sync(0xffffffffu, s, 16);
    const float inv = 1.f / s;

    const int LS[4] = {0, 4096, 5120, 5376};
    const int WI[4] = {64, 32, 16, 8};

    float4 acc = make_float4(0.f, 0.f, 0.f, 0.f);
    #pragma unroll
    for (int l = 0; l < 4; ++l) {
        const int   Wi = WI[l], ls = LS[l];
        const float Wf = (float)Wi;
        const float2 o = *(const float2*)(off + (l * 4 + p4) * 2);
        const float x = fmaf(rx[l], Wf, o.x) - 0.5f;
        const float y = fmaf(ry[l], Wf, o.y) - 0.5f;
        const float xf = floorf(x), yf = floorf(y);
        const int x0 = (int)xf, y0 = (int)yf;
        const float fx = x - xf, fy = y - yf;
        const float vx0 = ((unsigned)x0       < (unsigned)Wi) ? 1.f : 0.f;
        const float vx1 = ((unsigned)(x0 + 1) < (unsigned)Wi) ? 1.f : 0.f;
        const float vy0 = ((unsigned)y0       < (unsigned)Wi) ? 1.f : 0.f;
        const float vy1 = ((unsigned)(y0 + 1) < (unsigned)Wi) ? 1.f : 0.f;
        const int x0c = min(max(x0, 0), Wi - 1), x1c = min(max(x0 + 1, 0), Wi - 1);
        const int y0c = min(max(y0, 0), Wi - 1), y1c = min(max(y0 + 1, 0), Wi - 1);

        const float wp  = e[l] * inv;
        const float wx0 = (1.f - fx) * vx0,      wx1 = fx * vx1;
        const float wy0 = (1.f - fy) * vy0 * wp, wy1 = fy * vy1 * wp;
        const float wa = wx0 * wy0, wb = wx0 * wy1, wc = wx1 * wy0, wd = wx1 * wy1;

        const float* row0 = vb + (size_t)(ls + y0c * Wi) * EMBED;
        const float* row1 = vb + (size_t)(ls + y1c * Wi) * EMBED;
        const int c0 = x0c * EMBED, c1 = x1c * EMBED;
        const float4 v00 = *(const float4*)(row0 + c0);
        const float4 v01 = *(const float4*)(row0 + c1);
        const float4 v10 = *(const float4*)(row1 + c0);
        const float4 v11 = *(const float4*)(row1 + c1);

        acc.x = fmaf(wa, v00.x, fmaf(wb, v10.x, fmaf(wc, v01.x, fmaf(wd, v11.x, acc.x))));
        acc.y = fmaf(wa, v00.y, fmaf(wb, v10.y, fmaf(wc, v01.y, fmaf(wd, v11.y, acc.y))));
        acc.z = fmaf(wa, v00.z, fmaf(wb, v10.z, fmaf(wc, v01.z, fmaf(wd, v11.z, acc.z))));
        acc.w = fmaf(wa, v00.w, fmaf(wb, v10.w, fmaf(wc, v01.w, fmaf(wd, v11.w, acc.w))));
    }

    acc.x += __shfl_xor_sync(0xffffffffu, acc.x, 8);
    acc.y += __shfl_xor_sync(0xffffffffu, acc.y, 8);
    acc.z += __shfl_xor_sync(0xffffffffu, acc.z, 8);
    acc.w += __shfl_xor_sync(0xffffffffu, acc.w, 8);
    acc.x += __shfl_xor_sync(0xffffffffu, acc.x, 16);
    acc.y += __shfl_xor_sync(0xffffffffu, acc.y, 16);
    acc.z += __shfl_xor_sync(0xffffffffu, acc.z, 16);
    acc.w += __shfl_xor_sync(0xffffffffu, acc.w, 16);

    if (p4 == 0)
        *(float4*)(samp + (size_t)bq * EMBED + h * CDIM + cg * 4) = acc;
}

// ---------------- Launch ----------------
extern "C" void kernel_launch(void* const* d_in, const int* in_sizes, int n_in,
                              void* d_out, int out_size)
{
    const float* query   = (const float*)d_in[0];
    const float* ref_pts = (const float*)d_in[1];
    const float* value   = (const float*)d_in[2];
    const float* vproj_w = (const float*)d_in[5];
    const float* vproj_b = (const float*)d_in[6];
    const float* off_w   = (const float*)d_in[7];
    const float* off_b   = (const float*)d_in[8];
    const float* attn_w  = (const float*)d_in[9];
    const float* attn_b  = (const float*)d_in[10];
    const float* out_w   = (const float*)d_in[11];
    const float* out_b   = (const float*)d_in[12];
    float* out = (float*)d_out;

    float *pv, *poff, *pawl, *psamp;
    cudaGetSymbolAddress((void**)&pv,    g_v);
    cudaGetSymbolAddress((void**)&poff,  g_off);
    cudaGetSymbolAddress((void**)&pawl,  g_awl);
    cudaGetSymbolAddress((void**)&psamp, g_samp);
    __nv_bfloat16 *a0h, *a0l, *a1h, *a1l, *wth, *wtl;
    cudaGetSymbolAddress((void**)&a0h, g_a0h);
    cudaGetSymbolAddress((void**)&a0l, g_a0l);
    cudaGetSymbolAddress((void**)&a1h, g_a1h);
    cudaGetSymbolAddress((void**)&a1l, g_a1l);
    cudaGetSymbolAddress((void**)&wth, g_wth);
    cudaGetSymbolAddress((void**)&wtl, g_wtl);

    // weight transpose+split (tiny)
    conv_wt<<<dim3(256, 4), 256>>>(vproj_w, off_w, attn_w, out_w);
    // activation split: value -> slot0, query -> slot1
    conv_act<<<dim3(MROWS * EMBED / 1024, 2), 256>>>(value, query, a0h, a0l, a1h, a1l);

    // GEMM1: v = value @ vproj_w + b
    gemm_bf16split<<<dim3(MROWS / 128, 4), 256>>>(a0h, a0l, wth, wtl, vproj_b, pv, 256);
    // GEMM2: off = query @ off_w + b
    gemm_bf16split<<<dim3(MROWS / 128, 4), 256>>>(a1h, a1l, wth + 65536, wtl + 65536, off_b, poff, 256);
    // GEMM3: awl = query @ attn_w + b
    gemm_bf16split<<<dim3(MROWS / 128, 2), 256>>>(a1h, a1l, wth + 131072, wtl + 131072, attn_b, pawl, 128);

    // sampling
    msda_sample<<<MROWS, 256>>>(ref_pts, psamp);

    // samp split (reuse slot0) + out GEMM
    conv_act<<<dim3(MROWS * EMBED / 1024, 1), 256>>>(psamp, psamp, a0h, a0l, a0h, a0l);
    gemm_bf16split<<<dim3(MROWS / 128, 4), 256>>>(a0h, a0l, wth + 163840, wtl + 163840, out_b, out, 256);
}

// round 7
// speedup vs baseline: 1.7219x; 1.7219x over previous
#include <cuda_runtime.h>
#include <cuda_bf16.h>
#include <cuda_fp16.h>
#include <cstdint>

// ---------------- Problem constants ----------------
#define EMBED   256
#define HEADS   8
#define LEVELS  4
#define POINTS  4
#define CDIM    32
#define LEN_V   5440
#define LEN_Q   5440
#define BSZ     4
#define MROWS   (BSZ * LEN_Q)   // 21760

// ---------------- Scratch ----------------
__device__ __half g_vh [(size_t)MROWS * EMBED];   // projected value, fp16
__device__ float  g_off[(size_t)MROWS * EMBED];
__device__ float  g_awl[(size_t)MROWS * 128];

// split-bf16 activations: slot0 = value (later reused for samp), slot1 = query
__device__ __nv_bfloat16 g_a0h[(size_t)MROWS * EMBED];
__device__ __nv_bfloat16 g_a0l[(size_t)MROWS * EMBED];
__device__ __nv_bfloat16 g_a1h[(size_t)MROWS * EMBED];
__device__ __nv_bfloat16 g_a1l[(size_t)MROWS * EMBED];

// transposed split weights [N,K] bf16: vproj:0, off:65536, attn:131072, out:163840
// (off+attn contiguous => merged 384-row region at 65536)
__device__ __nv_bfloat16 g_wth[229376];
__device__ __nv_bfloat16 g_wtl[229376];

// ---------------- PTX helpers (generic ISA only) ----------------
__device__ __forceinline__ uint32_t smem_u32(const void* p) {
    uint32_t a;
    asm("{ .reg .u64 t; cvta.to.shared.u64 t, %1; cvt.u32.u64 %0, t; }" : "=r"(a) : "l"(p));
    return a;
}
__device__ __forceinline__ void ldm_x4(uint32_t* r, uint32_t addr) {
    asm volatile("ldmatrix.sync.aligned.m8n8.x4.shared.b16 {%0,%1,%2,%3}, [%4];"
        : "=r"(r[0]), "=r"(r[1]), "=r"(r[2]), "=r"(r[3]) : "r"(addr));
}
__device__ __forceinline__ void mma16816(float* c, const uint32_t* a, const uint32_t* b) {
    asm volatile(
        "mma.sync.aligned.m16n8k16.row.col.f32.bf16.bf16.f32 "
        "{%0,%1,%2,%3}, {%4,%5,%6,%7}, {%8,%9}, {%0,%1,%2,%3};"
        : "+f"(c[0]), "+f"(c[1]), "+f"(c[2]), "+f"(c[3])
        : "r"(a[0]), "r"(a[1]), "r"(a[2]), "r"(a[3]), "r"(b[0]), "r"(b[1]));
}
__device__ __forceinline__ void cp16(uint32_t dst, const void* src) {
    asm volatile("cp.async.cg.shared.global [%0], [%1], 16;" :: "r"(dst), "l"(src));
}
#define CP_COMMIT() asm volatile("cp.async.commit_group;" ::: "memory")

// swizzled smem offset (bf16 elements): row stride 64, 16B chunk xor (row&7)
__device__ __forceinline__ int swz(int row, int k) {
    return row * 64 + ((((k >> 3) ^ row) & 7) << 3) + (k & 7);
}

// stage layout (bytes): AH 0 (16K) | AL 16384 (16K) | BH 32768 (8K) | BL 40960 (8K)
#define STAGE_BYTES 49152
#define SM_TOTAL    (2 * STAGE_BYTES)   // 96 KB dynamic

// ---------------- GEMM: C[M,*] = A * W^T + bias, split-bf16 HMMA ------------
// BM=128, BN=64, BK=64, 256 thr = 8 warps (4m x 2n), warp tile 32x32, 2-stage
// cp.async pipeline. 3 passes: Ah*Bh + Ah*Bl + Al*Bh.
// MODE 0: fp32 C0. MODE 1: fp16 C0. MODE 2: dual (by<4 -> C0[256], else C1[128]).
template<int MODE>
__global__ __launch_bounds__(256)
void gemm_bf16split(const __nv_bfloat16* __restrict__ Ah, const __nv_bfloat16* __restrict__ Al,
                    const __nv_bfloat16* __restrict__ BTh, const __nv_bfloat16* __restrict__ BTl,
                    const float* __restrict__ bias0, const float* __restrict__ bias1,
                    void* __restrict__ C0, void* __restrict__ C1)
{
    extern __shared__ char sm[];
    const uint32_t uS = smem_u32(sm);

    const int tid  = threadIdx.x;
    const int lane = tid & 31;
    const int wid  = tid >> 5;
    const int wm   = wid & 3;
    const int wn   = wid >> 2;
    const int bm   = blockIdx.x * 128;
    const int bn   = blockIdx.y * 64;

    const __nv_bfloat16* pAh = Ah  + (size_t)bm * EMBED;
    const __nv_bfloat16* pAl = Al  + (size_t)bm * EMBED;
    const __nv_bfloat16* pBh = BTh + (size_t)bn * EMBED;
    const __nv_bfloat16* pBl = BTl + (size_t)bn * EMBED;

    const int grow = tid >> 3;      // 0..31
    const int gc8  = tid & 7;       // 16B chunk in 64-elem row
    const int gswz = swz(0, gc8 * 8) * 2;   // col part of swizzle, row added below

    float c[2][4][4];
    #pragma unroll
    for (int mt = 0; mt < 2; ++mt)
        #pragma unroll
        for (int nt = 0; nt < 4; ++nt)
            #pragma unroll
            for (int i = 0; i < 4; ++i) c[mt][nt][i] = 0.f;

    auto stage_load = [&](int kc, int s) {
        const uint32_t sb = uS + s * STAGE_BYTES;
        #pragma unroll
        for (int t = 0; t < 4; ++t) {
            const int row = grow + t * 32;
            const uint32_t so = (uint32_t)swz(row, gc8 * 8) * 2;
            cp16(sb + so,         pAh + (size_t)row * EMBED + kc * 64 + gc8 * 8);
            cp16(sb + 16384 + so, pAl + (size_t)row * EMBED + kc * 64 + gc8 * 8);
        }
        #pragma unroll
        for (int t = 0; t < 2; ++t) {
            const int row = grow + t * 32;
            const uint32_t so = (uint32_t)swz(row, gc8 * 8) * 2;
            cp16(sb + 32768 + so, pBh + (size_t)row * EMBED + kc * 64 + gc8 * 8);
            cp16(sb + 40960 + so, pBl + (size_t)row * EMBED + kc * 64 + gc8 * 8);
        }
        CP_COMMIT();
    };

    // fragment lane addressing
    const int a_r = (lane & 15);
    const int a_k = (lane >> 4) << 3;
    const int b_n = ((lane >> 4) << 3) + (lane & 7);
    const int b_k = ((lane >> 3) & 1) << 3;

    stage_load(0, 0);
    #pragma unroll
    for (int kc = 0; kc < 4; ++kc) {
        const int s = kc & 1;
        if (kc + 1 < 4) {
            stage_load(kc + 1, s ^ 1);
            asm volatile("cp.async.wait_group 1;" ::: "memory");
        } else {
            asm volatile("cp.async.wait_group 0;" ::: "memory");
        }
        __syncthreads();

        const uint32_t uAh = uS + s * STAGE_BYTES;
        const uint32_t uAl = uAh + 16384;
        const uint32_t uBh = uAh + 32768;
        const uint32_t uBl = uAh + 40960;

        #pragma unroll
        for (int ks = 0; ks < 4; ++ks) {
            uint32_t ah[2][4], al[2][4], bh[4][2], bl[4][2];
            #pragma unroll
            for (int mt = 0; mt < 2; ++mt) {
                const int r = wm * 32 + mt * 16 + a_r;
                const int k = ks * 16 + a_k;
                ldm_x4(ah[mt], uAh + swz(r, k) * 2);
                ldm_x4(al[mt], uAl + swz(r, k) * 2);
            }
            #pragma unroll
            for (int np = 0; np < 2; ++np) {
                const int n = wn * 32 + np * 16 + b_n;
                const int k = ks * 16 + b_k;
                uint32_t th[4], tl[4];
                ldm_x4(th, uBh + swz(n, k) * 2);
                ldm_x4(tl, uBl + swz(n, k) * 2);
                bh[np * 2 + 0][0] = th[0]; bh[np * 2 + 0][1] = th[1];
                bh[np * 2 + 1][0] = th[2]; bh[np * 2 + 1][1] = th[3];
                bl[np * 2 + 0][0] = tl[0]; bl[np * 2 + 0][1] = tl[1];
                bl[np * 2 + 1][0] = tl[2]; bl[np * 2 + 1][1] = tl[3];
            }
            #pragma unroll
            for (int mt = 0; mt < 2; ++mt)
                #pragma unroll
                for (int nt = 0; nt < 4; ++nt) {
                    mma16816(c[mt][nt], ah[mt], bh[nt]);
                    mma16816(c[mt][nt], ah[mt], bl[nt]);
                    mma16816(c[mt][nt], al[mt], bh[nt]);
                }
        }
        __syncthreads();
    }

    // ---- epilogue ----
    float* Cf = (float*)C0;
    const float* bs = bias0;
    int Nt = 256, colbase = bn;
    if (MODE == 2) {
        const bool isOff = (blockIdx.y < 4);
        Cf = isOff ? (float*)C0 : (float*)C1;
        bs = isOff ? bias0 : bias1;
        Nt = isOff ? 256 : 128;
        colbase = isOff ? bn : bn - 256;
    }

    #pragma unroll
    for (int mt = 0; mt < 2; ++mt) {
        const int r0 = bm + wm * 32 + mt * 16 + (lane >> 2);
        #pragma unroll
        for (int nt = 0; nt < 4; ++nt) {
            const int col = colbase + wn * 32 + nt * 8 + (lane & 3) * 2;
            const float2 bv = *(const float2*)(bs + col);
            const float o0x = c[mt][nt][0] + bv.x, o0y = c[mt][nt][1] + bv.y;
            const float o1x = c[mt][nt][2] + bv.x, o1y = c[mt][nt][3] + bv.y;
            if (MODE == 1) {
                __half* Ch = (__half*)C0;
                *(__half2*)(Ch + (size_t)r0 * 256 + col)       = __floats2half2_rn(o0x, o0y);
                *(__half2*)(Ch + (size_t)(r0 + 8) * 256 + col) = __floats2half2_rn(o1x, o1y);
            } else {
                *(float2*)(Cf + (size_t)r0 * Nt + col)       = make_float2(o0x, o0y);
                *(float2*)(Cf + (size_t)(r0 + 8) * Nt + col) = make_float2(o1x, o1y);
            }
        }
    }
}

// ---------------- split-bf16 conversions ----------------
__global__ __launch_bounds__(256)
void conv_act(const float* __restrict__ s0, const float* __restrict__ s1,
              __nv_bfloat16* __restrict__ d0h, __nv_bfloat16* __restrict__ d0l,
              __nv_bfloat16* __restrict__ d1h, __nv_bfloat16* __restrict__ d1l)
{
    const float* s = blockIdx.y ? s1 : s0;
    __nv_bfloat16* dh = blockIdx.y ? d1h : d0h;
    __nv_bfloat16* dl = blockIdx.y ? d1l : d0l;
    const size_t i = (size_t)blockIdx.x * 256 + threadIdx.x;
    float4 x = ((const float4*)s)[i];
    union { __nv_bfloat16 b[4]; uint2 u; } H, L;
    float xs[4] = {x.x, x.y, x.z, x.w};
    #pragma unroll
    for (int j = 0; j < 4; ++j) {
        H.b[j] = __float2bfloat16(xs[j]);
        L.b[j] = __float2bfloat16(xs[j] - __bfloat162float(H.b[j]));
    }
    ((uint2*)dh)[i] = H.u;
    ((uint2*)dl)[i] = L.u;
}

// transpose + split weights: out[n*256 + k] = W[k*N + n]
__global__ __launch_bounds__(256)
void conv_wt(const float* __restrict__ w0, const float* __restrict__ w1,
             const float* __restrict__ w2, const float* __restrict__ w3)
{
    const int m = blockIdx.y;
    const float* W = (m == 0) ? w0 : (m == 1) ? w1 : (m == 2) ? w2 : w3;
    const int N   = (m == 2) ? 128 : 256;
    const int off = (m == 0) ? 0 : (m == 1) ? 65536 : (m == 2) ? 131072 : 163840;
    const int idx = blockIdx.x * 256 + threadIdx.x;
    if (idx >= N * 256) return;
    const int k = idx & 255, n = idx >> 8;
    const float x = W[(size_t)k * N + n];
    __nv_bfloat16 h = __float2bfloat16(x);
    g_wth[off + idx] = h;
    g_wtl[off + idx] = __float2bfloat16(x - __bfloat162float(h));
}

// ---------------- Sampling kernel (fp16 v, bf16 hi/lo samp output) ----------
__global__ __launch_bounds__(256)
void msda_sample(const float* __restrict__ ref,
                 __nv_bfloat16* __restrict__ sh, __nv_bfloat16* __restrict__ sl)
{
    const int bq   = blockIdx.x;
    const int b    = bq / LEN_Q;
    const int h    = threadIdx.x >> 5;
    const int lane = threadIdx.x & 31;
    const int p4   = lane >> 3;
    const int cg   = lane & 7;

    const float*  off = g_off + (size_t)bq * EMBED + h * 32;
    const float*  awl = g_awl + (size_t)bq * 128 + h * 16;
    const __half* vb  = g_vh + (size_t)b * LEN_V * EMBED + h * CDIM + cg * 4;
    const float*  rp  = ref + (size_t)bq * 8;

    float4 r01 = ((const float4*)rp)[0];
    float4 r23 = ((const float4*)rp)[1];
    const float rx[4] = {r01.x, r01.z, r23.x, r23.z};
    const float ry[4] = {r01.y, r01.w, r23.y, r23.w};

    float e[4];
    e[0] = awl[p4]; e[1] = awl[4 + p4]; e[2] = awl[8 + p4]; e[3] = awl[12 + p4];
    float mx = fmaxf(fmaxf(e[0], e[1]), fmaxf(e[2], e[3]));
    mx = fmaxf(mx, __shfl_xor_sync(0xffffffffu, mx, 8));
    mx = fmaxf(mx, __shfl_xor_sync(0xffffffffu, mx, 16));
    float s = 0.f;
    #pragma unroll
    for (int l = 0; l < 4; ++l) { e[l] = __expf(e[l] - mx); s += e[l]; }
    s += __shfl_xor_sync(0xffffffffu, s, 8);
    s += __shfl_xor_sync(0xffffffffu, s, 16);
    const float inv = 1.f / s;

    const int LS[4] = {0, 4096, 5120, 5376};
    const int WI[4] = {64, 32, 16, 8};

    float4 acc = make_float4(0.f, 0.f, 0.f, 0.f);
    #pragma unroll
    for (int l = 0; l < 4; ++l) {
        const int   Wi = WI[l], ls = LS[l];
        const float Wf = (float)Wi;
        const float2 o = *(const float2*)(off + (l * 4 + p4) * 2);
        const float x = fmaf(rx[l], Wf, o.x) - 0.5f;
        const float y = fmaf(ry[l], Wf, o.y) - 0.5f;
        const float xf = floorf(x), yf = floorf(y);
        const int x0 = (int)xf, y0 = (int)yf;
        const float fx = x - xf, fy = y - yf;
        const float vx0 = ((unsigned)x0       < (unsigned)Wi) ? 1.f : 0.f;
        const float vx1 = ((unsigned)(x0 + 1) < (unsigned)Wi) ? 1.f : 0.f;
        const float vy0 = ((unsigned)y0       < (unsigned)Wi) ? 1.f : 0.f;
        const float vy1 = ((unsigned)(y0 + 1) < (unsigned)Wi) ? 1.f : 0.f;
        const int x0c = min(max(x0, 0), Wi - 1), x1c = min(max(x0 + 1, 0), Wi - 1);
        const int y0c = min(max(y0, 0), Wi - 1), y1c = min(max(y0 + 1, 0), Wi - 1);

        const float wp  = e[l] * inv;
        const float wx0 = (1.f - fx) * vx0,      wx1 = fx * vx1;
        const float wy0 = (1.f - fy) * vy0 * wp, wy1 = fy * vy1 * wp;
        const float wa = wx0 * wy0, wb = wx0 * wy1, wc = wx1 * wy0, wd = wx1 * wy1;

        const __half* row0 = vb + (size_t)(ls + y0c * Wi) * EMBED;
        const __half* row1 = vb + (size_t)(ls + y1c * Wi) * EMBED;
        const int c0 = x0c * EMBED, c1 = x1c * EMBED;

        const uint2 u00 = *(const uint2*)(row0 + c0);
        const uint2 u01 = *(const uint2*)(row0 + c1);
        const uint2 u10 = *(const uint2*)(row1 + c0);
        const uint2 u11 = *(const uint2*)(row1 + c1);

        const float2 a00 = __half22float2(*(const __half2*)&u00.x);
        const float2 b00 = __half22float2(*(const __half2*)&u00.y);
        const float2 a01 = __half22float2(*(const __half2*)&u01.x);
        const float2 b01 = __half22float2(*(const __half2*)&u01.y);
        const float2 a10 = __half22float2(*(const __half2*)&u10.x);
        const float2 b10 = __half22float2(*(const __half2*)&u10.y);
        const float2 a11 = __half22float2(*(const __half2*)&u11.x);
        const float2 b11 = __half22float2(*(const __half2*)&u11.y);

        acc.x = fmaf(wa, a00.x, fmaf(wb, a10.x, fmaf(wc, a01.x, fmaf(wd, a11.x, acc.x))));
        acc.y = fmaf(wa, a00.y, fmaf(wb, a10.y, fmaf(wc, a01.y, fmaf(wd, a11.y, acc.y))));
        acc.z = fmaf(wa, b00.x, fmaf(wb, b10.x, fmaf(wc, b01.x, fmaf(wd, b11.x, acc.z))));
        acc.w = fmaf(wa, b00.y, fmaf(wb, b10.y, fmaf(wc, b01.y, fmaf(wd, b11.y, acc.w))));
    }

    acc.x += __shfl_xor_sync(0xffffffffu, acc.x, 8);
    acc.y += __shfl_xor_sync(0xffffffffu, acc.y, 8);
    acc.z += __shfl_xor_sync(0xffffffffu, acc.z, 8);
    acc.w += __shfl_xor_sync(0xffffffffu, acc.w, 8);
    acc.x += __shfl_xor_sync(0xffffffffu, acc.x, 16);
    acc.y += __shfl_xor_sync(0xffffffffu, acc.y, 16);
    acc.z += __shfl_xor_sync(0xffffffffu, acc.z, 16);
    acc.w += __shfl_xor_sync(0xffffffffu, acc.w, 16);

    if (p4 == 0) {
        union { __nv_bfloat16 b[4]; uint2 u; } H, L;
        float xs[4] = {acc.x, acc.y, acc.z, acc.w};
        #pragma unroll
        for (int j = 0; j < 4; ++j) {
            H.b[j] = __float2bfloat16(xs[j]);
            L.b[j] = __float2bfloat16(xs[j] - __bfloat162float(H.b[j]));
        }
        const size_t idx = ((size_t)bq * EMBED + h * CDIM + cg * 4) / 2;
        ((uint2*)sh)[idx / 2] = H.u;
        ((uint2*)sl)[idx / 2] = L.u;
    }
}

// ---------------- Launch ----------------
extern "C" void kernel_launch(void* const* d_in, const int* in_sizes, int n_in,
                              void* d_out, int out_size)
{
    const float* query   = (const float*)d_in[0];
    const float* ref_pts = (const float*)d_in[1];
    const float* value   = (const float*)d_in[2];
    const float* vproj_w = (const float*)d_in[5];
    const float* vproj_b = (const float*)d_in[6];
    const float* off_w   = (const float*)d_in[7];
    const float* off_b   = (const float*)d_in[8];
    const float* attn_w  = (const float*)d_in[9];
    const float* attn_b  = (const float*)d_in[10];
    const float* out_w   = (const float*)d_in[11];
    const float* out_b   = (const float*)d_in[12];
    float* out = (float*)d_out;

    __half* pvh;
    float *poff, *pawl;
    cudaGetSymbolAddress((void**)&pvh,  g_vh);
    cudaGetSymbolAddress((void**)&poff, g_off);
    cudaGetSymbolAddress((void**)&pawl, g_awl);
    __nv_bfloat16 *a0h, *a0l, *a1h, *a1l, *wth, *wtl;
    cudaGetSymbolAddress((void**)&a0h, g_a0h);
    cudaGetSymbolAddress((void**)&a0l, g_a0l);
    cudaGetSymbolAddress((void**)&a1h, g_a1h);
    cudaGetSymbolAddress((void**)&a1l, g_a1l);
    cudaGetSymbolAddress((void**)&wth, g_wth);
    cudaGetSymbolAddress((void**)&wtl, g_wtl);

    cudaFuncSetAttribute(gemm_bf16split<0>, cudaFuncAttributeMaxDynamicSharedMemorySize, SM_TOTAL);
    cudaFuncSetAttribute(gemm_bf16split<1>, cudaFuncAttributeMaxDynamicSharedMemorySize, SM_TOTAL);
    cudaFuncSetAttribute(gemm_bf16split<2>, cudaFuncAttributeMaxDynamicSharedMemorySize, SM_TOTAL);

    // weight transpose+split
    conv_wt<<<dim3(256, 4), 256>>>(vproj_w, off_w, attn_w, out_w);
    // activation split: value -> slot0, query -> slot1
    conv_act<<<dim3(MROWS * EMBED / 1024, 2), 256>>>(value, query, a0h, a0l, a1h, a1l);

    // GEMM1: v = value @ vproj_w + b  -> fp16
    gemm_bf16split<1><<<dim3(MROWS / 128, 4), 256, SM_TOTAL>>>(
        a0h, a0l, wth, wtl, vproj_b, nullptr, pvh, nullptr);
    // GEMM2+3 merged: [off | awl] = query @ [off_w | attn_w] + b
    gemm_bf16split<2><<<dim3(MROWS / 128, 6), 256, SM_TOTAL>>>(
        a1h, a1l, wth + 65536, wtl + 65536, off_b, attn_b, poff, pawl);

    // sampling (writes bf16 hi/lo samp directly into slot0)
    msda_sample<<<MROWS, 256>>>(ref_pts, a0h, a0l);

    // out GEMM
    gemm_bf16split<0><<<dim3(MROWS / 128, 4), 256, SM_TOTAL>>>(
        a0h, a0l, wth + 163840, wtl + 163840, out_b, nullptr, out, nullptr);
}

// round 10
// speedup vs baseline: 1.9343x; 1.1233x over previous
#include <cuda_runtime.h>
#include <cuda_bf16.h>
#include <cuda_fp16.h>
#include <cstdint>

// ---------------- Problem constants ----------------
#define EMBED   256
#define HEADS   8
#define LEVELS  4
#define POINTS  4
#define CDIM    32
#define LEN_V   5440
#define LEN_Q   5440
#define BSZ     4
#define MROWS   (BSZ * LEN_Q)   // 21760

// ---------------- Scratch ----------------
__device__ __half g_vh [(size_t)MROWS * EMBED];   // projected value, fp16
__device__ float  g_off[(size_t)MROWS * EMBED];
__device__ float  g_awl[(size_t)MROWS * 128];

__device__ __half g_af0[(size_t)MROWS * EMBED];   // value  as fp16
__device__ __half g_af1[(size_t)MROWS * EMBED];   // query  as fp16

// sampler output, bf16 hi/lo (feeds the split out-proj)
__device__ __nv_bfloat16 g_a0h[(size_t)MROWS * EMBED];
__device__ __nv_bfloat16 g_a0l[(size_t)MROWS * EMBED];

// fp16 transposed weights [N,K]: vproj:0, off:65536, attn:131072, out:163840
__device__ __half g_wh[229376];
// bf16 hi/lo split of out_w only (transposed [256,256])
__device__ __nv_bfloat16 g_wth[65536];
__device__ __nv_bfloat16 g_wtl[65536];

// ---------------- PTX helpers (generic ISA only) ----------------
__device__ __forceinline__ uint32_t smem_u32(const void* p) {
    uint32_t a;
    asm("{ .reg .u64 t; cvta.to.shared.u64 t, %1; cvt.u32.u64 %0, t; }" : "=r"(a) : "l"(p));
    return a;
}
__device__ __forceinline__ void ldm_x4(uint32_t* r, uint32_t addr) {
    asm volatile("ldmatrix.sync.aligned.m8n8.x4.shared.b16 {%0,%1,%2,%3}, [%4];"
        : "=r"(r[0]), "=r"(r[1]), "=r"(r[2]), "=r"(r[3]) : "r"(addr));
}
__device__ __forceinline__ void mma_bf16(float* c, const uint32_t* a, const uint32_t* b) {
    asm volatile(
        "mma.sync.aligned.m16n8k16.row.col.f32.bf16.bf16.f32 "
        "{%0,%1,%2,%3}, {%4,%5,%6,%7}, {%8,%9}, {%0,%1,%2,%3};"
        : "+f"(c[0]), "+f"(c[1]), "+f"(c[2]), "+f"(c[3])
        : "r"(a[0]), "r"(a[1]), "r"(a[2]), "r"(a[3]), "r"(b[0]), "r"(b[1]));
}
__device__ __forceinline__ void mma_f16(float* c, const uint32_t* a, const uint32_t* b) {
    asm volatile(
        "mma.sync.aligned.m16n8k16.row.col.f32.f16.f16.f32 "
        "{%0,%1,%2,%3}, {%4,%5,%6,%7}, {%8,%9}, {%0,%1,%2,%3};"
        : "+f"(c[0]), "+f"(c[1]), "+f"(c[2]), "+f"(c[3])
        : "r"(a[0]), "r"(a[1]), "r"(a[2]), "r"(a[3]), "r"(b[0]), "r"(b[1]));
}
__device__ __forceinline__ void cp16(uint32_t dst, const void* src) {
    asm volatile("cp.async.cg.shared.global [%0], [%1], 16;" :: "r"(dst), "l"(src));
}
#define CP_COMMIT() asm volatile("cp.async.commit_group;" ::: "memory")

// swizzled smem offset (16-bit elements): row stride 64, 16B chunk xor (row&7)
__device__ __forceinline__ int swz(int row, int k) {
    return row * 64 + ((((k >> 3) ^ row) & 7) << 3) + (k & 7);
}

// ====================== single-pass fp16 GEMM ================================
// BM=128, BN=64, BK=64, 256 thr = 8 warps (4m x 2n), warp 32x32, 2-stage cp.async.
// MODE 1: fp16 C0 (N=256). MODE 2: dual fp32 (by<4 -> C0[256], else C1[128]).
#define F16_STAGE 24576
#define F16_SMEM  (2 * F16_STAGE)   // 48 KB

template<int MODE>
__global__ __launch_bounds__(256)
void gemm_f16(const __half* __restrict__ A, const __half* __restrict__ BT,
              const float* __restrict__ bias0, const float* __restrict__ bias1,
              void* __restrict__ C0, void* __restrict__ C1)
{
    extern __shared__ char sm[];
    const uint32_t uS = smem_u32(sm);

    const int tid  = threadIdx.x;
    const int lane = tid & 31;
    const int wid  = tid >> 5;
    const int wm   = wid & 3;
    const int wn   = wid >> 2;
    const int bm   = blockIdx.x * 128;
    const int bn   = blockIdx.y * 64;

    const __half* pA = A  + (size_t)bm * EMBED;
    const __half* pB = BT + (size_t)bn * EMBED;

    const int grow = tid >> 3;
    const int gc8  = tid & 7;

    float c[2][4][4];
    #pragma unroll
    for (int mt = 0; mt < 2; ++mt)
        #pragma unroll
        for (int nt = 0; nt < 4; ++nt)
            #pragma unroll
            for (int i = 0; i < 4; ++i) c[mt][nt][i] = 0.f;

    auto stage_load = [&](int kc, int s) {
        const uint32_t sb = uS + s * F16_STAGE;
        #pragma unroll
        for (int t = 0; t < 4; ++t) {
            const int row = grow + t * 32;
            cp16(sb + (uint32_t)swz(row, gc8 * 8) * 2,
                 pA + (size_t)row * EMBED + kc * 64 + gc8 * 8);
        }
        #pragma unroll
        for (int t = 0; t < 2; ++t) {
            const int row = grow + t * 32;
            cp16(sb + 16384 + (uint32_t)swz(row, gc8 * 8) * 2,
                 pB + (size_t)row * EMBED + kc * 64 + gc8 * 8);
        }
        CP_COMMIT();
    };

    const int a_r = (lane & 15);
    const int a_k = (lane >> 4) << 3;
    const int b_n = ((lane >> 4) << 3) + (lane & 7);
    const int b_k = ((lane >> 3) & 1) << 3;

    stage_load(0, 0);
    #pragma unroll
    for (int kc = 0; kc < 4; ++kc) {
        const int s = kc & 1;
        if (kc + 1 < 4) {
            stage_load(kc + 1, s ^ 1);
            asm volatile("cp.async.wait_group 1;" ::: "memory");
        } else {
            asm volatile("cp.async.wait_group 0;" ::: "memory");
        }
        __syncthreads();

        const uint32_t uA = uS + s * F16_STAGE;
        const uint32_t uB = uA + 16384;

        #pragma unroll
        for (int ks = 0; ks < 4; ++ks) {
            uint32_t a[2][4], b[4][2];
            #pragma unroll
            for (int mt = 0; mt < 2; ++mt)
                ldm_x4(a[mt], uA + swz(wm * 32 + mt * 16 + a_r, ks * 16 + a_k) * 2);
            #pragma unroll
            for (int np = 0; np < 2; ++np) {
                uint32_t t4[4];
                ldm_x4(t4, uB + swz(wn * 32 + np * 16 + b_n, ks * 16 + b_k) * 2);
                b[np * 2 + 0][0] = t4[0]; b[np * 2 + 0][1] = t4[1];
                b[np * 2 + 1][0] = t4[2]; b[np * 2 + 1][1] = t4[3];
            }
            #pragma unroll
            for (int mt = 0; mt < 2; ++mt)
                #pragma unroll
                for (int nt = 0; nt < 4; ++nt)
                    mma_f16(c[mt][nt], a[mt], b[nt]);
        }
        __syncthreads();
    }

    // ---- epilogue ----
    float* Cf = (float*)C0;
    const float* bs = bias0;
    int Nt = 256, colbase = bn;
    if (MODE == 2) {
        const bool isOff = (blockIdx.y < 4);
        Cf = isOff ? (float*)C0 : (float*)C1;
        bs = isOff ? bias0 : bias1;
        Nt = isOff ? 256 : 128;
        colbase = isOff ? bn : bn - 256;
    }
    #pragma unroll
    for (int mt = 0; mt < 2; ++mt) {
        const int r0 = bm + wm * 32 + mt * 16 + (lane >> 2);
        #pragma unroll
        for (int nt = 0; nt < 4; ++nt) {
            const int col = colbase + wn * 32 + nt * 8 + (lane & 3) * 2;
            const float2 bv = *(const float2*)(bs + col);
            const float o0x = c[mt][nt][0] + bv.x, o0y = c[mt][nt][1] + bv.y;
            const float o1x = c[mt][nt][2] + bv.x, o1y = c[mt][nt][3] + bv.y;
            if (MODE == 1) {
                __half* Ch = (__half*)C0;
                *(__half2*)(Ch + (size_t)r0 * 256 + col)       = __floats2half2_rn(o0x, o0y);
                *(__half2*)(Ch + (size_t)(r0 + 8) * 256 + col) = __floats2half2_rn(o1x, o1y);
            } else {
                *(float2*)(Cf + (size_t)r0 * Nt + col)       = make_float2(o0x, o0y);
                *(float2*)(Cf + (size_t)(r0 + 8) * Nt + col) = make_float2(o1x, o1y);
            }
        }
    }
}

// ====================== 3-pass bf16-split GEMM (out-proj only) ===============
#define BS_STAGE 49152
#define BS_SMEM  (2 * BS_STAGE)   // 96 KB

__global__ __launch_bounds__(256)
void gemm_bf16split(const __nv_bfloat16* __restrict__ Ah, const __nv_bfloat16* __restrict__ Al,
                    const __nv_bfloat16* __restrict__ BTh, const __nv_bfloat16* __restrict__ BTl,
                    const float* __restrict__ bias, float* __restrict__ C)
{
    extern __shared__ char sm[];
    const uint32_t uS = smem_u32(sm);

    const int tid  = threadIdx.x;
    const int lane = tid & 31;
    const int wid  = tid >> 5;
    const int wm   = wid & 3;
    const int wn   = wid >> 2;
    const int bm   = blockIdx.x * 128;
    const int bn   = blockIdx.y * 64;

    const __nv_bfloat16* pAh = Ah  + (size_t)bm * EMBED;
    const __nv_bfloat16* pAl = Al  + (size_t)bm * EMBED;
    const __nv_bfloat16* pBh = BTh + (size_t)bn * EMBED;
    const __nv_bfloat16* pBl = BTl + (size_t)bn * EMBED;

    const int grow = tid >> 3;
    const int gc8  = tid & 7;

    float c[2][4][4];
    #pragma unroll
    for (int mt = 0; mt < 2; ++mt)
        #pragma unroll
        for (int nt = 0; nt < 4; ++nt)
            #pragma unroll
            for (int i = 0; i < 4; ++i) c[mt][nt][i] = 0.f;

    auto stage_load = [&](int kc, int s) {
        const uint32_t sb = uS + s * BS_STAGE;
        #pragma unroll
        for (int t = 0; t < 4; ++t) {
            const int row = grow + t * 32;
            const uint32_t so = (uint32_t)swz(row, gc8 * 8) * 2;
            cp16(sb + so,         pAh + (size_t)row * EMBED + kc * 64 + gc8 * 8);
            cp16(sb + 16384 + so, pAl + (size_t)row * EMBED + kc * 64 + gc8 * 8);
        }
        #pragma unroll
        for (int t = 0; t < 2; ++t) {
            const int row = grow + t * 32;
            const uint32_t so = (uint32_t)swz(row, gc8 * 8) * 2;
            cp16(sb + 32768 + so, pBh + (size_t)row * EMBED + kc * 64 + gc8 * 8);
            cp16(sb + 40960 + so, pBl + (size_t)row * EMBED + kc * 64 + gc8 * 8);
        }
        CP_COMMIT();
    };

    const int a_r = (lane & 15);
    const int a_k = (lane >> 4) << 3;
    const int b_n = ((lane >> 4) << 3) + (lane & 7);
    const int b_k = ((lane >> 3) & 1) << 3;

    stage_load(0, 0);
    #pragma unroll
    for (int kc = 0; kc < 4; ++kc) {
        const int s = kc & 1;
        if (kc + 1 < 4) {
            stage_load(kc + 1, s ^ 1);
            asm volatile("cp.async.wait_group 1;" ::: "memory");
        } else {
            asm volatile("cp.async.wait_group 0;" ::: "memory");
        }
        __syncthreads();

        const uint32_t uAh = uS + s * BS_STAGE;
        const uint32_t uAl = uAh + 16384;
        const uint32_t uBh = uAh + 32768;
        const uint32_t uBl = uAh + 40960;

        #pragma unroll
        for (int ks = 0; ks < 4; ++ks) {
            uint32_t ah[2][4], al[2][4], bh[4][2], bl[4][2];
            #pragma unroll
            for (int mt = 0; mt < 2; ++mt) {
                ldm_x4(ah[mt], uAh + swz(wm * 32 + mt * 16 + a_r, ks * 16 + a_k) * 2);
                ldm_x4(al[mt], uAl + swz(wm * 32 + mt * 16 + a_r, ks * 16 + a_k) * 2);
            }
            #pragma unroll
            for (int np = 0; np < 2; ++np) {
                uint32_t th[4], tl[4];
                ldm_x4(th, uBh + swz(wn * 32 + np * 16 + b_n, ks * 16 + b_k) * 2);
                ldm_x4(tl, uBl + swz(wn * 32 + np * 16 + b_n, ks * 16 + b_k) * 2);
                bh[np * 2 + 0][0] = th[0]; bh[np * 2 + 0][1] = th[1];
                bh[np * 2 + 1][0] = th[2]; bh[np * 2 + 1][1] = th[3];
                bl[np * 2 + 0][0] = tl[0]; bl[np * 2 + 0][1] = tl[1];
                bl[np * 2 + 1][0] = tl[2]; bl[np * 2 + 1][1] = tl[3];
            }
            #pragma unroll
            for (int mt = 0; mt < 2; ++mt)
                #pragma unroll
                for (int nt = 0; nt < 4; ++nt) {
                    mma_bf16(c[mt][nt], ah[mt], bh[nt]);
                    mma_bf16(c[mt][nt], ah[mt], bl[nt]);
                    mma_bf16(c[mt][nt], al[mt], bh[nt]);
                }
        }
        __syncthreads();
    }

    #pragma unroll
    for (int mt = 0; mt < 2; ++mt) {
        const int r0 = bm + wm * 32 + mt * 16 + (lane >> 2);
        #pragma unroll
        for (int nt = 0; nt < 4; ++nt) {
            const int col = bn + wn * 32 + nt * 8 + (lane & 3) * 2;
            const float2 bv = *(const float2*)(bias + col);
            *(float2*)(C + (size_t)r0 * 256 + col) =
                make_float2(c[mt][nt][0] + bv.x, c[mt][nt][1] + bv.y);
            *(float2*)(C + (size_t)(r0 + 8) * 256 + col) =
                make_float2(c[mt][nt][2] + bv.x, c[mt][nt][3] + bv.y);
        }
    }
}

// ---------------- conversions ----------------
__global__ __launch_bounds__(256)
void conv_act(const float* __restrict__ s0, const float* __restrict__ s1,
              __half* __restrict__ d0, __half* __restrict__ d1)
{
    const float* s = blockIdx.y ? s1 : s0;
    __half* d = blockIdx.y ? d1 : d0;
    const size_t i = (size_t)blockIdx.x * 256 + threadIdx.x;
    float4 x = ((const float4*)s)[i];
    union { __half2 h[2]; uint2 u; } U;
    U.h[0] = __floats2half2_rn(x.x, x.y);
    U.h[1] = __floats2half2_rn(x.z, x.w);
    ((uint2*)d)[i] = U.u;
}

// transpose: g_wh[off + n*256 + k] = W[k*N + n]; also bf16 split for out_w
__global__ __launch_bounds__(256)
void conv_wt(const float* __restrict__ w0, const float* __restrict__ w1,
             const float* __restrict__ w2, const float* __restrict__ w3)
{
    const int m = blockIdx.y;
    const float* W = (m == 0) ? w0 : (m == 1) ? w1 : (m == 2) ? w2 : w3;
    const int N   = (m == 2) ? 128 : 256;
    const int off = (m == 0) ? 0 : (m == 1) ? 65536 : (m == 2) ? 131072 : 163840;
    const int idx = blockIdx.x * 256 + threadIdx.x;
    if (idx >= N * 256) return;
    const int k = idx & 255, n = idx >> 8;
    const float x = W[(size_t)k * N + n];
    g_wh[off + idx] = __float2half(x);
    if (m == 3) {
        __nv_bfloat16 h = __float2bfloat16(x);
        g_wth[idx] = h;
        g_wtl[idx] = __float2bfloat16(x - __bfloat162float(h));
    }
}

// ---------------- Sampling kernel (fp16 v, bf16 hi/lo samp output) ----------
__global__ __launch_bounds__(256)
void msda_sample(const float* __restrict__ ref,
                 __nv_bfloat16* __restrict__ sh, __nv_bfloat16* __restrict__ sl)
{
    const int bq   = blockIdx.x;
    const int b    = bq / LEN_Q;
    const int h    = threadIdx.x >> 5;
    const int lane = threadIdx.x & 31;
    const int p4   = lane >> 3;
    const int cg   = lane & 7;

    const float*  off = g_off + (size_t)bq * EMBED + h * 32;
    const float*  awl = g_awl + (size_t)bq * 128 + h * 16;
    const __half* vb  = g_vh + (size_t)b * LEN_V * EMBED + h * CDIM + cg * 4;
    const float*  rp  = ref + (size_t)bq * 8;

    float4 r01 = ((const float4*)rp)[0];
    float4 r23 = ((const float4*)rp)[1];
    const float rx[4] = {r01.x, r01.z, r23.x, r23.z};
    const float ry[4] = {r01.y, r01.w, r23.y, r23.w};

    float e[4];
    e[0] = awl[p4]; e[1] = awl[4 + p4]; e[2] = awl[8 + p4]; e[3] = awl[12 + p4];
    float mx = fmaxf(fmaxf(e[0], e[1]), fmaxf(e[2], e[3]));
    mx = fmaxf(mx, __shfl_xor_sync(0xffffffffu, mx, 8));
    mx = fmaxf(mx, __shfl_xor_sync(0xffffffffu, mx, 16));
    float s = 0.f;
    #pragma unroll
    for (int l = 0; l < 4; ++l) { e[l] = __expf(e[l] - mx); s += e[l]; }
    s += __shfl_xor_sync(0xffffffffu, s, 8);
    s += __shfl_xor_sync(0xffffffffu, s, 16);
    const float inv = 1.f / s;

    const int LS[4] = {0, 4096, 5120, 5376};
    const int WI[4] = {64, 32, 16, 8};

    float4 acc = make_float4(0.f, 0.f, 0.f, 0.f);
    #pragma unroll
    for (int l = 0; l < 4; ++l) {
        const int   Wi = WI[l], ls = LS[l];
        const float Wf = (float)Wi;
        const float2 o = *(const float2*)(off + (l * 4 + p4) * 2);
        const float x = fmaf(rx[l], Wf, o.x) - 0.5f;
        const float y = fmaf(ry[l], Wf, o.y) - 0.5f;
        const float xf = floorf(x), yf = floorf(y);
        const int x0 = (int)xf, y0 = (int)yf;
        const float fx = x - xf, fy = y - yf;
        const float vx0 = ((unsigned)x0       < (unsigned)Wi) ? 1.f : 0.f;
        const float vx1 = ((unsigned)(x0 + 1) < (unsigned)Wi) ? 1.f : 0.f;
        const float vy0 = ((unsigned)y0       < (unsigned)Wi) ? 1.f : 0.f;
        const float vy1 = ((unsigned)(y0 + 1) < (unsigned)Wi) ? 1.f : 0.f;
        const int x0c = min(max(x0, 0), Wi - 1), x1c = min(max(x0 + 1, 0), Wi - 1);
        const int y0c = min(max(y0, 0), Wi - 1), y1c = min(max(y0 + 1, 0), Wi - 1);

        const float wp  = e[l] * inv;
        const float wx0 = (1.f - fx) * vx0,      wx1 = fx * vx1;
        const float wy0 = (1.f - fy) * vy0 * wp, wy1 = fy * vy1 * wp;
        const float wa = wx0 * wy0, wb = wx0 * wy1, wc = wx1 * wy0, wd = wx1 * wy1;

        const __half* row0 = vb + (size_t)(ls + y0c * Wi) * EMBED;
        const __half* row1 = vb + (size_t)(ls + y1c * Wi) * EMBED;
        const int c0 = x0c * EMBED, c1 = x1c * EMBED;

        const uint2 u00 = *(const uint2*)(row0 + c0);
        const uint2 u01 = *(const uint2*)(row0 + c1);
        const uint2 u10 = *(const uint2*)(row1 + c0);
        const uint2 u11 = *(const uint2*)(row1 + c1);

        const float2 a00 = __half22float2(*(const __half2*)&u00.x);
        const float2 b00 = __half22float2(*(const __half2*)&u00.y);
        const float2 a01 = __half22float2(*(const __half2*)&u01.x);
        const float2 b01 = __half22float2(*(const __half2*)&u01.y);
        const float2 a10 = __half22float2(*(const __half2*)&u10.x);
        const float2 b10 = __half22float2(*(const __half2*)&u10.y);
        const float2 a11 = __half22float2(*(const __half2*)&u11.x);
        const float2 b11 = __half22float2(*(const __half2*)&u11.y);

        acc.x = fmaf(wa, a00.x, fmaf(wb, a10.x, fmaf(wc, a01.x, fmaf(wd, a11.x, acc.x))));
        acc.y = fmaf(wa, a00.y, fmaf(wb, a10.y, fmaf(wc, a01.y, fmaf(wd, a11.y, acc.y))));
        acc.z = fmaf(wa, b00.x, fmaf(wb, b10.x, fmaf(wc, b01.x, fmaf(wd, b11.x, acc.z))));
        acc.w = fmaf(wa, b00.y, fmaf(wb, b10.y, fmaf(wc, b01.y, fmaf(wd, b11.y, acc.w))));
    }

    acc.x += __shfl_xor_sync(0xffffffffu, acc.x, 8);
    acc.y += __shfl_xor_sync(0xffffffffu, acc.y, 8);
    acc.z += __shfl_xor_sync(0xffffffffu, acc.z, 8);
    acc.w += __shfl_xor_sync(0xffffffffu, acc.w, 8);
    acc.x += __shfl_xor_sync(0xffffffffu, acc.x, 16);
    acc.y += __shfl_xor_sync(0xffffffffu, acc.y, 16);
    acc.z += __shfl_xor_sync(0xffffffffu, acc.z, 16);
    acc.w += __shfl_xor_sync(0xffffffffu, acc.w, 16);

    if (p4 == 0) {
        union { __nv_bfloat16 b[4]; uint2 u; } H, L;
        float xs[4] = {acc.x, acc.y, acc.z, acc.w};
        #pragma unroll
        for (int j = 0; j < 4; ++j) {
            H.b[j] = __float2bfloat16(xs[j]);
            L.b[j] = __float2bfloat16(xs[j] - __bfloat162float(H.b[j]));
        }
        const size_t vecidx = ((size_t)bq * EMBED + h * CDIM + cg * 4) / 4;
        ((uint2*)sh)[vecidx] = H.u;
        ((uint2*)sl)[vecidx] = L.u;
    }
}

// ---------------- Launch ----------------
extern "C" void kernel_launch(void* const* d_in, const int* in_sizes, int n_in,
                              void* d_out, int out_size)
{
    const float* query   = (const float*)d_in[0];
    const float* ref_pts = (const float*)d_in[1];
    const float* value   = (const float*)d_in[2];
    const float* vproj_w = (const float*)d_in[5];
    const float* vproj_b = (const float*)d_in[6];
    const float* off_w   = (const float*)d_in[7];
    const float* off_b   = (const float*)d_in[8];
    const float* attn_w  = (const float*)d_in[9];
    const float* attn_b  = (const float*)d_in[10];
    const float* out_w   = (const float*)d_in[11];
    const float* out_b   = (const float*)d_in[12];
    float* out = (float*)d_out;

    __half *pvh, *paf0, *paf1, *pwh;
    float *poff, *pawl;
    cudaGetSymbolAddress((void**)&pvh,  g_vh);
    cudaGetSymbolAddress((void**)&poff, g_off);
    cudaGetSymbolAddress((void**)&pawl, g_awl);
    cudaGetSymbolAddress((void**)&paf0, g_af0);
    cudaGetSymbolAddress((void**)&paf1, g_af1);
    cudaGetSymbolAddress((void**)&pwh,  g_wh);
    __nv_bfloat16 *a0h, *a0l, *wth, *wtl;
    cudaGetSymbolAddress((void**)&a0h, g_a0h);
    cudaGetSymbolAddress((void**)&a0l, g_a0l);
    cudaGetSymbolAddress((void**)&wth, g_wth);
    cudaGetSymbolAddress((void**)&wtl, g_wtl);

    cudaFuncSetAttribute(gemm_f16<1>, cudaFuncAttributeMaxDynamicSharedMemorySize, F16_SMEM);
    cudaFuncSetAttribute(gemm_f16<2>, cudaFuncAttributeMaxDynamicSharedMemorySize, F16_SMEM);
    cudaFuncSetAttribute(gemm_bf16split, cudaFuncAttributeMaxDynamicSharedMemorySize, BS_SMEM);

    // weight transpose (+ bf16 split for out_w)
    conv_wt<<<dim3(256, 4), 256>>>(vproj_w, off_w, attn_w, out_w);
    // activations fp32 -> fp16
    conv_act<<<dim3(MROWS * EMBED / 1024, 2), 256>>>(value, query, paf0, paf1);

    // GEMM1: v = value @ vproj_w + b  -> fp16
    gemm_f16<1><<<dim3(MROWS / 128, 4), 256, F16_SMEM>>>(
        paf0, pwh, vproj_b, nullptr, pvh, nullptr);
    // GEMM2+3 merged: [off | awl] = query @ [off_w | attn_w] + b
    gemm_f16<2><<<dim3(MROWS / 128, 6), 256, F16_SMEM>>>(
        paf1, pwh + 65536, off_b, attn_b, poff, pawl);

    // sampling (writes bf16 hi/lo samp)
    msda_sample<<<MROWS, 256>>>(ref_pts, a0h, a0l);

    // out GEMM (3-pass split, precision hedge)
    gemm_bf16split<<<dim3(MROWS / 128, 4), 256, BS_SMEM>>>(
        a0h, a0l, wth, wtl, out_b, out);
}

// round 11
// speedup vs baseline: 2.2163x; 1.1458x over previous
#include <cuda_runtime.h>
#include <cuda_bf16.h>
#include <cuda_fp16.h>
#include <cstdint>

// ---------------- Problem constants ----------------
#define EMBED   256
#define HEADS   8
#define LEVELS  4
#define POINTS  4
#define CDIM    32
#define LEN_V   5440
#define LEN_Q   5440
#define BSZ     4
#define MROWS   (BSZ * LEN_Q)   // 21760

// ---------------- Scratch ----------------
__device__ __half g_vh [(size_t)MROWS * EMBED];   // projected value, fp16
__device__ float  g_off[(size_t)MROWS * EMBED];
__device__ float  g_awl[(size_t)MROWS * 128];

__device__ __half g_af0[(size_t)MROWS * EMBED];   // value fp16, later samp fp16
__device__ __half g_af1[(size_t)MROWS * EMBED];   // query fp16

// fp16 transposed weights [N,K]: vproj:0, off:65536, attn:131072, out:163840
__device__ __half g_wh[229376];

// ---------------- PTX helpers (generic ISA only) ----------------
__device__ __forceinline__ uint32_t smem_u32(const void* p) {
    uint32_t a;
    asm("{ .reg .u64 t; cvta.to.shared.u64 t, %1; cvt.u32.u64 %0, t; }" : "=r"(a) : "l"(p));
    return a;
}
__device__ __forceinline__ void ldm_x4(uint32_t* r, uint32_t addr) {
    asm volatile("ldmatrix.sync.aligned.m8n8.x4.shared.b16 {%0,%1,%2,%3}, [%4];"
        : "=r"(r[0]), "=r"(r[1]), "=r"(r[2]), "=r"(r[3]) : "r"(addr));
}
__device__ __forceinline__ void mma_f16(float* c, const uint32_t* a, const uint32_t* b) {
    asm volatile(
        "mma.sync.aligned.m16n8k16.row.col.f32.f16.f16.f32 "
        "{%0,%1,%2,%3}, {%4,%5,%6,%7}, {%8,%9}, {%0,%1,%2,%3};"
        : "+f"(c[0]), "+f"(c[1]), "+f"(c[2]), "+f"(c[3])
        : "r"(a[0]), "r"(a[1]), "r"(a[2]), "r"(a[3]), "r"(b[0]), "r"(b[1]));
}
__device__ __forceinline__ void cp16(uint32_t dst, const void* src) {
    asm volatile("cp.async.cg.shared.global [%0], [%1], 16;" :: "r"(dst), "l"(src));
}
#define CP_COMMIT() asm volatile("cp.async.commit_group;" ::: "memory")

// swizzled smem offset (16-bit elements): row stride 64, 16B chunk xor (row&7)
__device__ __forceinline__ int swz(int row, int k) {
    return row * 64 + ((((k >> 3) ^ row) & 7) << 3) + (k & 7);
}

// ====================== single-pass fp16 GEMM ================================
// BM=128, BN=64, BK=64, 256 thr = 8 warps (4m x 2n), warp 32x32, 3-stage cp.async.
// MODE 0: fp32 C0 (N=256). MODE 1: fp16 C0 (N=256).
// MODE 2: dual fp32 (by<4 -> C0[256], else C1[128]).
#define F16_STAGE 24576
#define F16_SMEM  (3 * F16_STAGE)   // 72 KB

template<int MODE>
__global__ __launch_bounds__(256)
void gemm_f16(const __half* __restrict__ A, const __half* __restrict__ BT,
              const float* __restrict__ bias0, const float* __restrict__ bias1,
              void* __restrict__ C0, void* __restrict__ C1)
{
    extern __shared__ char sm[];
    const uint32_t uS = smem_u32(sm);

    const int tid  = threadIdx.x;
    const int lane = tid & 31;
    const int wid  = tid >> 5;
    const int wm   = wid & 3;
    const int wn   = wid >> 2;
    const int bm   = blockIdx.x * 128;
    const int bn   = blockIdx.y * 64;

    const __half* pA = A  + (size_t)bm * EMBED;
    const __half* pB = BT + (size_t)bn * EMBED;

    const int grow = tid >> 3;
    const int gc8  = tid & 7;

    float c[2][4][4];
    #pragma unroll
    for (int mt = 0; mt < 2; ++mt)
        #pragma unroll
        for (int nt = 0; nt < 4; ++nt)
            #pragma unroll
            for (int i = 0; i < 4; ++i) c[mt][nt][i] = 0.f;

    auto stage_load = [&](int kc, int s) {
        const uint32_t sb = uS + s * F16_STAGE;
        #pragma unroll
        for (int t = 0; t < 4; ++t) {
            const int row = grow + t * 32;
            cp16(sb + (uint32_t)swz(row, gc8 * 8) * 2,
                 pA + (size_t)row * EMBED + kc * 64 + gc8 * 8);
        }
        #pragma unroll
        for (int t = 0; t < 2; ++t) {
            const int row = grow + t * 32;
            cp16(sb + 16384 + (uint32_t)swz(row, gc8 * 8) * 2,
                 pB + (size_t)row * EMBED + kc * 64 + gc8 * 8);
        }
        CP_COMMIT();
    };

    const int a_r = (lane & 15);
    const int a_k = (lane >> 4) << 3;
    const int b_n = ((lane >> 4) << 3) + (lane & 7);
    const int b_k = ((lane >> 3) & 1) << 3;

    stage_load(0, 0);
    stage_load(1, 1);
    #pragma unroll
    for (int kc = 0; kc < 4; ++kc) {
        const int s = kc % 3;
        if (kc < 2) {
            stage_load(kc + 2, (kc + 2) % 3);
            asm volatile("cp.async.wait_group 2;" ::: "memory");
        } else if (kc == 2) {
            asm volatile("cp.async.wait_group 1;" ::: "memory");
        } else {
            asm volatile("cp.async.wait_group 0;" ::: "memory");
        }
        __syncthreads();

        const uint32_t uA = uS + s * F16_STAGE;
        const uint32_t uB = uA + 16384;

        #pragma unroll
        for (int ks = 0; ks < 4; ++ks) {
            uint32_t a[2][4], b[4][2];
            #pragma unroll
            for (int mt = 0; mt < 2; ++mt)
                ldm_x4(a[mt], uA + swz(wm * 32 + mt * 16 + a_r, ks * 16 + a_k) * 2);
            #pragma unroll
            for (int np = 0; np < 2; ++np) {
                uint32_t t4[4];
                ldm_x4(t4, uB + swz(wn * 32 + np * 16 + b_n, ks * 16 + b_k) * 2);
                b[np * 2 + 0][0] = t4[0]; b[np * 2 + 0][1] = t4[1];
                b[np * 2 + 1][0] = t4[2]; b[np * 2 + 1][1] = t4[3];
            }
            #pragma unroll
            for (int mt = 0; mt < 2; ++mt)
                #pragma unroll
                for (int nt = 0; nt < 4; ++nt)
                    mma_f16(c[mt][nt], a[mt], b[nt]);
        }
        __syncthreads();
    }

    // ---- epilogue ----
    float* Cf = (float*)C0;
    const float* bs = bias0;
    int Nt = 256, colbase = bn;
    if (MODE == 2) {
        const bool isOff = (blockIdx.y < 4);
        Cf = isOff ? (float*)C0 : (float*)C1;
        bs = isOff ? bias0 : bias1;
        Nt = isOff ? 256 : 128;
        colbase = isOff ? bn : bn - 256;
    }
    #pragma unroll
    for (int mt = 0; mt < 2; ++mt) {
        const int r0 = bm + wm * 32 + mt * 16 + (lane >> 2);
        #pragma unroll
        for (int nt = 0; nt < 4; ++nt) {
            const int col = colbase + wn * 32 + nt * 8 + (lane & 3) * 2;
            const float2 bv = *(const float2*)(bs + col);
            const float o0x = c[mt][nt][0] + bv.x, o0y = c[mt][nt][1] + bv.y;
            const float o1x = c[mt][nt][2] + bv.x, o1y = c[mt][nt][3] + bv.y;
            if (MODE == 1) {
                __half* Ch = (__half*)C0;
                *(__half2*)(Ch + (size_t)r0 * 256 + col)       = __floats2half2_rn(o0x, o0y);
                *(__half2*)(Ch + (size_t)(r0 + 8) * 256 + col) = __floats2half2_rn(o1x, o1y);
            } else {
                *(float2*)(Cf + (size_t)r0 * Nt + col)       = make_float2(o0x, o0y);
                *(float2*)(Cf + (size_t)(r0 + 8) * Nt + col) = make_float2(o1x, o1y);
            }
        }
    }
}

// ---------------- conversions ----------------
__global__ __launch_bounds__(256)
void conv_act(const float* __restrict__ s0, const float* __restrict__ s1,
              __half* __restrict__ d0, __half* __restrict__ d1)
{
    const float* s = blockIdx.y ? s1 : s0;
    __half* d = blockIdx.y ? d1 : d0;
    const size_t i = (size_t)blockIdx.x * 256 + threadIdx.x;
    float4 x = ((const float4*)s)[i];
    union { __half2 h[2]; uint2 u; } U;
    U.h[0] = __floats2half2_rn(x.x, x.y);
    U.h[1] = __floats2half2_rn(x.z, x.w);
    ((uint2*)d)[i] = U.u;
}

// transpose: g_wh[off + n*256 + k] = W[k*N + n]
__global__ __launch_bounds__(256)
void conv_wt(const float* __restrict__ w0, const float* __restrict__ w1,
             const float* __restrict__ w2, const float* __restrict__ w3)
{
    const int m = blockIdx.y;
    const float* W = (m == 0) ? w0 : (m == 1) ? w1 : (m == 2) ? w2 : w3;
    const int N   = (m == 2) ? 128 : 256;
    const int off = (m == 0) ? 0 : (m == 1) ? 65536 : (m == 2) ? 131072 : 163840;
    const int idx = blockIdx.x * 256 + threadIdx.x;
    if (idx >= N * 256) return;
    const int k = idx & 255, n = idx >> 8;
    g_wh[off + idx] = __float2half(W[(size_t)k * N + n]);
}

// ---------------- Sampling kernel (fp16 v, fp16 samp output) ----------------
__global__ __launch_bounds__(256)
void msda_sample(const float* __restrict__ ref, __half* __restrict__ samp)
{
    const int bq   = blockIdx.x;
    const int b    = bq / LEN_Q;
    const int h    = threadIdx.x >> 5;
    const int lane = threadIdx.x & 31;
    const int p4   = lane >> 3;
    const int cg   = lane & 7;

    const float*  off = g_off + (size_t)bq * EMBED + h * 32;
    const float*  awl = g_awl + (size_t)bq * 128 + h * 16;
    const __half* vb  = g_vh + (size_t)b * LEN_V * EMBED + h * CDIM + cg * 4;
    const float*  rp  = ref + (size_t)bq * 8;

    float4 r01 = ((const float4*)rp)[0];
    float4 r23 = ((const float4*)rp)[1];
    const float rx[4] = {r01.x, r01.z, r23.x, r23.z};
    const float ry[4] = {r01.y, r01.w, r23.y, r23.w};

    float e[4];
    e[0] = awl[p4]; e[1] = awl[4 + p4]; e[2] = awl[8 + p4]; e[3] = awl[12 + p4];
    float mx = fmaxf(fmaxf(e[0], e[1]), fmaxf(e[2], e[3]));
    mx = fmaxf(mx, __shfl_xor_sync(0xffffffffu, mx, 8));
    mx = fmaxf(mx, __shfl_xor_sync(0xffffffffu, mx, 16));
    float s = 0.f;
    #pragma unroll
    for (int l = 0; l < 4; ++l) { e[l] = __expf(e[l] - mx); s += e[l]; }
    s += __shfl_xor_sync(0xffffffffu, s, 8);
    s += __shfl_xor_sync(0xffffffffu, s, 16);
    const float inv = 1.f / s;

    const int LS[4] = {0, 4096, 5120, 5376};
    const int WI[4] = {64, 32, 16, 8};

    float4 acc = make_float4(0.f, 0.f, 0.f, 0.f);
    #pragma unroll
    for (int l = 0; l < 4; ++l) {
        const int   Wi = WI[l], ls = LS[l];
        const float Wf = (float)Wi;
        const float2 o = *(const float2*)(off + (l * 4 + p4) * 2);
        const float x = fmaf(rx[l], Wf, o.x) - 0.5f;
        const float y = fmaf(ry[l], Wf, o.y) - 0.5f;
        const float xf = floorf(x), yf = floorf(y);
        const int x0 = (int)xf, y0 = (int)yf;
        const float fx = x - xf, fy = y - yf;
        const float vx0 = ((unsigned)x0       < (unsigned)Wi) ? 1.f : 0.f;
        const float vx1 = ((unsigned)(x0 + 1) < (unsigned)Wi) ? 1.f : 0.f;
        const float vy0 = ((unsigned)y0       < (unsigned)Wi) ? 1.f : 0.f;
        const float vy1 = ((unsigned)(y0 + 1) < (unsigned)Wi) ? 1.f : 0.f;
        const int x0c = min(max(x0, 0), Wi - 1), x1c = min(max(x0 + 1, 0), Wi - 1);
        const int y0c = min(max(y0, 0), Wi - 1), y1c = min(max(y0 + 1, 0), Wi - 1);

        const float wp  = e[l] * inv;
        const float wx0 = (1.f - fx) * vx0,      wx1 = fx * vx1;
        const float wy0 = (1.f - fy) * vy0 * wp, wy1 = fy * vy1 * wp;
        const float wa = wx0 * wy0, wb = wx0 * wy1, wc = wx1 * wy0, wd = wx1 * wy1;

        const __half* row0 = vb + (size_t)(ls + y0c * Wi) * EMBED;
        const __half* row1 = vb + (size_t)(ls + y1c * Wi) * EMBED;
        const int c0 = x0c * EMBED, c1 = x1c * EMBED;

        const uint2 u00 = *(const uint2*)(row0 + c0);
        const uint2 u01 = *(const uint2*)(row0 + c1);
        const uint2 u10 = *(const uint2*)(row1 + c0);
        const uint2 u11 = *(const uint2*)(row1 + c1);

        const float2 a00 = __half22float2(*(const __half2*)&u00.x);
        const float2 b00 = __half22float2(*(const __half2*)&u00.y);
        const float2 a01 = __half22float2(*(const __half2*)&u01.x);
        const float2 b01 = __half22float2(*(const __half2*)&u01.y);
        const float2 a10 = __half22float2(*(const __half2*)&u10.x);
        const float2 b10 = __half22float2(*(const __half2*)&u10.y);
        const float2 a11 = __half22float2(*(const __half2*)&u11.x);
        const float2 b11 = __half22float2(*(const __half2*)&u11.y);

        acc.x = fmaf(wa, a00.x, fmaf(wb, a10.x, fmaf(wc, a01.x, fmaf(wd, a11.x, acc.x))));
        acc.y = fmaf(wa, a00.y, fmaf(wb, a10.y, fmaf(wc, a01.y, fmaf(wd, a11.y, acc.y))));
        acc.z = fmaf(wa, b00.x, fmaf(wb, b10.x, fmaf(wc, b01.x, fmaf(wd, b11.x, acc.z))));
        acc.w = fmaf(wa, b00.y, fmaf(wb, b10.y, fmaf(wc, b01.y, fmaf(wd, b11.y, acc.w))));
    }

    acc.x += __shfl_xor_sync(0xffffffffu, acc.x, 8);
    acc.y += __shfl_xor_sync(0xffffffffu, acc.y, 8);
    acc.z += __shfl_xor_sync(0xffffffffu, acc.z, 8);
    acc.w += __shfl_xor_sync(0xffffffffu, acc.w, 8);
    acc.x += __shfl_xor_sync(0xffffffffu, acc.x, 16);
    acc.y += __shfl_xor_sync(0xffffffffu, acc.y, 16);
    acc.z += __shfl_xor_sync(0xffffffffu, acc.z, 16);
    acc.w += __shfl_xor_sync(0xffffffffu, acc.w, 16);

    if (p4 == 0) {
        union { __half2 h[2]; uint2 u; } U;
        U.h[0] = __floats2half2_rn(acc.x, acc.y);
        U.h[1] = __floats2half2_rn(acc.z, acc.w);
        const size_t vecidx = ((size_t)bq * EMBED + h * CDIM + cg * 4) / 4;
        ((uint2*)samp)[vecidx] = U.u;
    }
}

// ---------------- Launch ----------------
extern "C" void kernel_launch(void* const* d_in, const int* in_sizes, int n_in,
                              void* d_out, int out_size)
{
    const float* query   = (const float*)d_in[0];
    const float* ref_pts = (const float*)d_in[1];
    const float* value   = (const float*)d_in[2];
    const float* vproj_w = (const float*)d_in[5];
    const float* vproj_b = (const float*)d_in[6];
    const float* off_w   = (const float*)d_in[7];
    const float* off_b   = (const float*)d_in[8];
    const float* attn_w  = (const float*)d_in[9];
    const float* attn_b  = (const float*)d_in[10];
    const float* out_w   = (const float*)d_in[11];
    const float* out_b   = (const float*)d_in[12];
    float* out = (float*)d_out;

    __half *pvh, *paf0, *paf1, *pwh;
    float *poff, *pawl;
    cudaGetSymbolAddress((void**)&pvh,  g_vh);
    cudaGetSymbolAddress((void**)&poff, g_off);
    cudaGetSymbolAddress((void**)&pawl, g_awl);
    cudaGetSymbolAddress((void**)&paf0, g_af0);
    cudaGetSymbolAddress((void**)&paf1, g_af1);
    cudaGetSymbolAddress((void**)&pwh,  g_wh);

    cudaFuncSetAttribute(gemm_f16<0>, cudaFuncAttributeMaxDynamicSharedMemorySize, F16_SMEM);
    cudaFuncSetAttribute(gemm_f16<1>, cudaFuncAttributeMaxDynamicSharedMemorySize, F16_SMEM);
    cudaFuncSetAttribute(gemm_f16<2>, cudaFuncAttributeMaxDynamicSharedMemorySize, F16_SMEM);

    // weight transpose
    conv_wt<<<dim3(256, 4), 256>>>(vproj_w, off_w, attn_w, out_w);
    // activations fp32 -> fp16
    conv_act<<<dim3(MROWS * EMBED / 1024, 2), 256>>>(value, query, paf0, paf1);

    // GEMM1: v = value @ vproj_w + b  -> fp16
    gemm_f16<1><<<dim3(MROWS / 128, 4), 256, F16_SMEM>>>(
        paf0, pwh, vproj_b, nullptr, pvh, nullptr);
    // GEMM2+3 merged: [off | awl] = query @ [off_w | attn_w] + b
    gemm_f16<2><<<dim3(MROWS / 128, 6), 256, F16_SMEM>>>(
        paf1, pwh + 65536, off_b, attn_b, poff, pawl);

    // sampling (writes fp16 samp into g_af0, already consumed by GEMM1)
    msda_sample<<<MROWS, 256>>>(ref_pts, paf0);

    // out GEMM: out = samp @ out_w + b  (fp32 output)
    gemm_f16<0><<<dim3(MROWS / 128, 4), 256, F16_SMEM>>>(
        paf0, pwh + 163840, out_b, nullptr, out, nullptr);
}